// round 3
// baseline (speedup 1.0000x reference)
#include <cuda_runtime.h>

// out[g] = tanh( sum_{i<3} x[row_{3g+i}]·Wr + x[col_{3g+i}]·Wc )
// Phase1: u[n] = x[n]·Wr^T, v[n] = x[n]·Wc^T  (9 floats each, padded to 64B rows)
// Pack:   per-group index block, 8 ints, 32B aligned, prescaled elem offsets
// Phase2: warp per group; ONE LDG.128 gathers all 6 rows (4 lanes/row) ->
//         1 wavefront per row instead of 3; shfl_xor butterfly reduce; block-
//         staged coalesced tanh+store.

#define HID 128
#define PAD 16                     // floats per u/v row (64B: one L2 line half)
#define MAX_NODES 60000
#define MAX_GROUPS 320000
#define VOFF (MAX_NODES * PAD)     // v array base inside g_uv

__device__ float g_uv[2 * MAX_NODES * PAD];
__device__ int   g_gidx[MAX_GROUPS * 8];

// ---------------------------------------------------------------------------
// Fast tanh: tanh(t) = 1 - 2/(exp(2t)+1). Saturates correctly at +-inf.
// ---------------------------------------------------------------------------
__device__ __forceinline__ float tanh_fast(float t) {
    float e = __expf(2.0f * t);
    return 1.0f - __fdividef(2.0f, e + 1.0f);
}

// ---------------------------------------------------------------------------
// Fused prep kernel. Blocks [0, b1): phase1 projections. Blocks [b1, ..): pack.
// ---------------------------------------------------------------------------
__global__ void __launch_bounds__(256)
prep_kernel(const float* __restrict__ x, const float* __restrict__ W,
            const void* __restrict__ eidx,
            int n_nodes, int n_groups, int E, int b1) {
    if ((int)blockIdx.x < b1) {
        // ---- phase1: thread (n, j) computes u_j[n] AND v_j[n] (shared x row)
        __shared__ float ws[18 * 132];          // j<9: W[j,0:128]; j+9: W[j,128:256]
        for (int i = threadIdx.x; i < 18 * HID; i += 256) {
            int j = i / HID, k = i - j * HID;
            ws[j * 132 + k] = (j < 9) ? W[j * 256 + k] : W[(j - 9) * 256 + 128 + k];
        }
        __syncthreads();

        int tid = blockIdx.x * 256 + threadIdx.x;
        if (tid >= n_nodes * 9) return;
        int n = tid / 9;
        int j = tid - n * 9;

        const float4* xr = (const float4*)(x + (size_t)n * HID);
        const float4* w1 = (const float4*)(ws + j * 132);
        const float4* w2 = (const float4*)(ws + (j + 9) * 132);
        float a1 = 0.f, a2 = 0.f;
        #pragma unroll
        for (int i = 0; i < HID / 4; i++) {
            float4 xv = xr[i];
            float4 b1v = w1[i];
            float4 b2v = w2[i];
            a1 += xv.x * b1v.x; a1 += xv.y * b1v.y;
            a1 += xv.z * b1v.z; a1 += xv.w * b1v.w;
            a2 += xv.x * b2v.x; a2 += xv.y * b2v.y;
            a2 += xv.z * b2v.z; a2 += xv.w * b2v.w;
        }
        g_uv[n * PAD + j]        = a1;
        g_uv[VOFF + n * PAD + j] = a2;
    } else {
        // ---- pack: thread per group. Detect idx dtype via warp ballot on the
        // high words of the first 32 int64 slots (all-zero <=> int64).
        int lane = threadIdx.x & 31;
        unsigned hw = ((const unsigned*)eidx)[2 * lane + 1];
        bool is64 = (__ballot_sync(0xffffffffu, hw != 0u) == 0u);

        int g = (blockIdx.x - b1) * 256 + threadIdx.x;
        if (g >= n_groups) return;
        int e0 = 3 * g;
        int r[3], c[3];
        if (is64) {
            const long long* p = (const long long*)eidx;
            #pragma unroll
            for (int i = 0; i < 3; i++) {
                r[i] = (int)p[e0 + i];
                c[i] = (int)p[E + e0 + i];
            }
        } else {
            const int* p = (const int*)eidx;
            #pragma unroll
            for (int i = 0; i < 3; i++) {
                r[i] = p[e0 + i];
                c[i] = p[E + e0 + i];
            }
        }
        int* o = g_gidx + g * 8;
        #pragma unroll
        for (int i = 0; i < 3; i++) {
            o[i]     = min(max(r[i], 0), MAX_NODES - 1) * PAD;
            o[3 + i] = VOFF + min(max(c[i], 0), MAX_NODES - 1) * PAD;
        }
        o[6] = 0;
        o[7] = 0;
    }
}

// ---------------------------------------------------------------------------
// Phase2: warp per group (8 groups per 256-thread block, grid-stride).
// lane = i*4 + p (i = row slot 0..5, p = float4 part). One LDG.128 fetches all
// six 64B rows (each row = 1 line = 1 wavefront). shfl_xor over i-bits reduces.
// ---------------------------------------------------------------------------
__global__ void __launch_bounds__(256)
phase2_kernel(float* __restrict__ out, int n_groups) {
    __shared__ float stage[8 * 12];
    int warp = threadIdx.x >> 5;
    int lane = threadIdx.x & 31;
    int i = lane >> 2;
    int p = lane & 3;

    for (int gbase = blockIdx.x * 8; gbase < n_groups; gbase += gridDim.x * 8) {
        int g = gbase + warp;
        if (g < n_groups) {
            // 8 consecutive ints: one 32B line, one wavefront
            int off = 0;
            if (lane < 8) off = g_gidx[g * 8 + lane];
            int rowoff = __shfl_sync(0xffffffffu, off, i);

            float4 v = make_float4(0.f, 0.f, 0.f, 0.f);
            if (lane < 24)
                v = *(const float4*)(g_uv + rowoff + p * 4);

            // butterfly over i in lane bits [2:4] -> every lane holds sum_i
            #pragma unroll
            for (int m = 4; m <= 16; m <<= 1) {
                v.x += __shfl_xor_sync(0xffffffffu, v.x, m);
                v.y += __shfl_xor_sync(0xffffffffu, v.y, m);
                v.z += __shfl_xor_sync(0xffffffffu, v.z, m);
                v.w += __shfl_xor_sync(0xffffffffu, v.w, m);
            }
            // lanes 0..2 (p=0..2, i=0) stage acc[0..3],[4..7],[8,x,x,x]
            if (lane < 3)
                *(float4*)(stage + warp * 12 + lane * 4) = v;
        }
        __syncthreads();

        // coalesced tanh + store: 72 outputs for this block's 8 groups
        int t = threadIdx.x;
        if (t < 72) {
            int gl = t / 9;
            int j  = t - gl * 9;
            if (gbase + gl < n_groups)
                out[(size_t)gbase * 9 + t] = tanh_fast(stage[gl * 12 + j]);
        }
        __syncthreads();
    }
}

// ---------------------------------------------------------------------------
extern "C" void kernel_launch(void* const* d_in, const int* in_sizes, int n_in,
                              void* d_out, int out_size) {
    const float* x    = (const float*)d_in[0];   // [n_nodes, 128] fp32
    const float* W    = (const float*)d_in[1];   // [9, 256] fp32
    const void*  eidx = d_in[2];                 // [2, E] int32 or int64

    int n_nodes  = in_sizes[0] / HID;
    if (n_nodes > MAX_NODES) n_nodes = MAX_NODES;
    int n_groups = out_size / 9;
    if (n_groups > MAX_GROUPS) n_groups = MAX_GROUPS;
    int E = 3 * n_groups;

    int b1 = (n_nodes * 9 + 255) / 256;          // phase1 blocks
    int b2 = (n_groups + 255) / 256;             // pack blocks
    prep_kernel<<<b1 + b2, 256>>>(x, W, eidx, n_nodes, n_groups, E, b1);

    phase2_kernel<<<148 * 8, 256>>>((float*)d_out, n_groups);
}

// round 4
// speedup vs baseline: 1.8609x; 1.8609x over previous
#include <cuda_runtime.h>

// out[g] = tanh( sum_{i<3} x[row_{3g+i}]·Wr + x[col_{3g+i}]·Wc )
// Phase1 (smem-tiled): u[n]=x[n]·Wr^T, v[n]=x[n]·Wc^T, 64B-padded rows in g_uv.
// Phase2 (warp=8 groups, 4 lanes/group): 6 cross-LDG single-line-per-cluster
// gathers, register accumulate, FFMA-only tanh, smem-transposed STG.128.

#define HID 128
#define PAD 16
#define MAX_NODES 60000
#define VOFF (MAX_NODES * PAD)
#define FULL 0xffffffffu

__device__ float g_uv[2 * MAX_NODES * PAD];

// ---------------------------------------------------------------------------
// FFMA-only tanh. No MUFU. e^{2x} = 2^z, z = 2x*log2(e); round via magic add;
// 2^f degree-5 poly; scale by exponent bits; 1/(E+1) via bit-seed + 3 Newton.
// abs err < ~1e-5 over full range; saturates to +-1.
// ---------------------------------------------------------------------------
__device__ __forceinline__ float tanh_ffma(float xx) {
    float z = xx * 2.885390081777927f;            // 2*log2(e)
    z = fminf(fmaxf(z, -30.0f), 30.0f);
    float t = z + 12582912.0f;                    // 1.5*2^23: round-to-nearest
    float n = t - 12582912.0f;
    float f = z - n;                              // |f| <= 0.5
    float p =             1.3333558146e-3f;
    p = fmaf(p, f, 9.6181291076e-3f);
    p = fmaf(p, f, 5.5504108664e-2f);
    p = fmaf(p, f, 2.4022650696e-1f);
    p = fmaf(p, f, 6.9314718056e-1f);
    p = fmaf(p, f, 1.0f);                         // 2^f
    int i = __float_as_int(t) - 0x4B400000;       // rint(z) as int
    float scale = __int_as_float((i + 127) << 23);
    float E = p * scale;                          // e^{2x}
    float d = E + 1.0f;
    float r = __int_as_float(0x7EF311C3 - __float_as_int(d));
    r = r * fmaf(-d, r, 2.0f);
    r = r * fmaf(-d, r, 2.0f);
    r = r * fmaf(-d, r, 2.0f);                    // 1/d to ~1 ulp
    return fmaf(-2.0f, r, 1.0f);                  // 1 - 2/(e^{2x}+1)
}

// ---------------------------------------------------------------------------
// Phase1: 288 threads, 64-node tile staged coalesced into smem (x read once
// from DRAM). Thread = (node-pair, j): 2 nodes x (u_j, v_j); W rows shared
// across the pair -> LDS per FFMA halved.
// ---------------------------------------------------------------------------
__global__ void __launch_bounds__(288)
phase1_kernel(const float* __restrict__ x, const float* __restrict__ W,
              int n_nodes) {
    __shared__ float4 xs[64 * 33];    // 64 rows, 32 f4 + 1 pad
    __shared__ float4 wsf[18 * 33];   // j<9: W[j][0:128]; j+9: W[j][128:256]
    int t = threadIdx.x;

    const float4* Wf4 = (const float4*)W;
    for (int i = t; i < 18 * 32; i += 288) {
        int j = i >> 5, c = i & 31;
        wsf[j * 33 + c] = (j < 9) ? Wf4[j * 64 + c] : Wf4[(j - 9) * 64 + 32 + c];
    }

    int nbase = blockIdx.x * 64;
    int nvalid = n_nodes - nbase;
    if (nvalid > 64) nvalid = 64;
    int maxf4 = nvalid * 32;
    const float4* xf4 = (const float4*)x;
    for (int i = t; i < 64 * 32; i += 288) {
        int r = i >> 5, c = i & 31;
        float4 v = make_float4(0.f, 0.f, 0.f, 0.f);
        if (i < maxf4) v = xf4[(size_t)(nbase + r) * 32 + c];
        xs[r * 33 + c] = v;
    }
    __syncthreads();

    int np = t / 9;                 // node pair 0..31
    int j  = t - np * 9;            // output 0..8
    int n0 = np * 2, n1 = n0 + 1;

    float a0u = 0.f, a0v = 0.f, a1u = 0.f, a1v = 0.f;
    #pragma unroll
    for (int i = 0; i < 32; i++) {
        float4 w1 = wsf[j * 33 + i];
        float4 w2 = wsf[(j + 9) * 33 + i];
        float4 xa = xs[n0 * 33 + i];
        float4 xb = xs[n1 * 33 + i];
        a0u += xa.x * w1.x + xa.y * w1.y + xa.z * w1.z + xa.w * w1.w;
        a0v += xa.x * w2.x + xa.y * w2.y + xa.z * w2.z + xa.w * w2.w;
        a1u += xb.x * w1.x + xb.y * w1.y + xb.z * w1.z + xb.w * w1.w;
        a1v += xb.x * w2.x + xb.y * w2.y + xb.z * w2.z + xb.w * w2.w;
    }
    int na = nbase + n0, nb = nbase + n1;
    if (na < n_nodes) {
        g_uv[na * PAD + j]        = a0u;
        g_uv[VOFF + na * PAD + j] = a0v;
    }
    if (nb < n_nodes) {
        g_uv[nb * PAD + j]        = a1u;
        g_uv[VOFF + nb * PAD + j] = a1v;
    }
}

// ---------------------------------------------------------------------------
// Phase2: warp handles 8 groups; lane = grp*4 + p. Six separate LDG.128s
// (one per row slot), each hitting 8 distinct 64B rows -> cross-LDG 1.0cyc/wf.
// Sum over slots in registers; tanh; smem transpose; one STG.128 (288B/warp).
// ---------------------------------------------------------------------------
__global__ void __launch_bounds__(256)
phase2_kernel(const void* __restrict__ eidx, float* __restrict__ out,
              int n_groups, int E) {
    __shared__ float stage[8 * 72];
    int warp = threadIdx.x >> 5;
    int lane = threadIdx.x & 31;
    int grp  = lane >> 2;
    int p    = lane & 3;

    int gbase8 = ((int)blockIdx.x * 8 + warp) * 8;
    if (gbase8 >= n_groups) return;
    int gvalid = n_groups - gbase8;               // usually 8
    if (gvalid > 8) gvalid = 8;

    // dtype detect: odd 32-bit words of the first 32 int64 slots all-zero <=> int64
    unsigned hwp = ((const unsigned*)eidx)[2 * lane + 1];
    bool is64 = (__ballot_sync(FULL, hwp != 0u) == 0u);

    int e0 = gbase8 * 3;
    int nedge = gvalid * 3;
    int rv = 0, cv = 0;
    if (is64) {
        const long long* p64 = (const long long*)eidx;
        if (lane < nedge) {
            rv = (int)p64[e0 + lane];
            cv = (int)p64[(size_t)E + e0 + lane];
        }
    } else {
        const int* p32 = (const int*)eidx;
        if (lane < nedge) {
            rv = p32[e0 + lane];
            cv = p32[E + e0 + lane];
        }
    }
    int ro = min(max(rv, 0), MAX_NODES - 1) * PAD;
    int co = VOFF + min(max(cv, 0), MAX_NODES - 1) * PAD;

    float4 acc = make_float4(0.f, 0.f, 0.f, 0.f);
    #pragma unroll
    for (int i = 0; i < 3; i++) {
        int oR = __shfl_sync(FULL, ro, grp * 3 + i);
        int oC = __shfl_sync(FULL, co, grp * 3 + i);
        float4 a = *(const float4*)(g_uv + oR + p * 4);
        float4 b = *(const float4*)(g_uv + oC + p * 4);
        acc.x += a.x + b.x;
        acc.y += a.y + b.y;
        acc.z += a.z + b.z;
        acc.w += a.w + b.w;
    }

    float t0 = tanh_ffma(acc.x);
    float t1 = tanh_ffma(acc.y);
    float t2 = tanh_ffma(acc.z);
    float t3 = tanh_ffma(acc.w);

    // stage stride-9 (only j = 4p+q < 9 real)
    float* sw = stage + warp * 72;
    int base = grp * 9 + 4 * p;
    if (4 * p + 0 < 9) sw[base + 0] = t0;
    if (4 * p + 1 < 9) sw[base + 1] = t1;
    if (4 * p + 2 < 9) sw[base + 2] = t2;
    if (4 * p + 3 < 9) sw[base + 3] = t3;
    __syncwarp();

    // 72 contiguous floats -> 18-lane STG.128 (gbase8*36B is 16B-aligned)
    int nfl = gvalid * 9;
    if (lane < 18 && lane * 4 < nfl) {
        float4 v = *(const float4*)(sw + lane * 4);
        if (lane * 4 + 4 <= nfl) {
            *(float4*)(out + (size_t)gbase8 * 9 + lane * 4) = v;
        } else {
            float* o = out + (size_t)gbase8 * 9 + lane * 4;
            int rem = nfl - lane * 4;
            if (rem > 0) o[0] = v.x;
            if (rem > 1) o[1] = v.y;
            if (rem > 2) o[2] = v.z;
        }
    }
}

// ---------------------------------------------------------------------------
extern "C" void kernel_launch(void* const* d_in, const int* in_sizes, int n_in,
                              void* d_out, int out_size) {
    const float* x    = (const float*)d_in[0];   // [n_nodes, 128] fp32
    const float* W    = (const float*)d_in[1];   // [9, 256] fp32
    const void*  eidx = d_in[2];                 // [2, E] int32 or int64

    int n_nodes  = in_sizes[0] / HID;
    if (n_nodes > MAX_NODES) n_nodes = MAX_NODES;
    int n_groups = out_size / 9;
    int E = 3 * n_groups;

    phase1_kernel<<<(n_nodes + 63) / 64, 288>>>(x, W, n_nodes);
    phase2_kernel<<<(n_groups + 63) / 64, 256>>>(eidx, (float*)d_out,
                                                 n_groups, E);
}

// round 6
// speedup vs baseline: 2.2671x; 1.2183x over previous
#include <cuda_runtime.h>

// out[g] = tanh( sum_{i<3} x[row_{3g+i}]·Wr + x[col_{3g+i}]·Wc )
// Phase1: lane=2 nodes, broadcast-W from smem, fma.rn.f32x2 packed FMA.
// Phase2: warp=16 groups (2 clusters of 8), 12 hoisted gather LDG.128s,
//         Pade tanh predicated to valid j, coalesced staged stores.

#define HID 128
#define PAD 16
#define MAX_NODES 60000
#define VOFF (MAX_NODES * PAD)
#define FULL 0xffffffffu

__device__ float g_uv[2 * MAX_NODES * PAD];

// ---- f32x2 packed helpers ----
__device__ __forceinline__ double pk2(float lo, float hi) {
    double d;
    asm("mov.b64 %0, {%1, %2};" : "=d"(d) : "f"(lo), "f"(hi));
    return d;
}
__device__ __forceinline__ void upk2(double d, float& lo, float& hi) {
    asm("mov.b64 {%0, %1}, %2;" : "=f"(lo), "=f"(hi) : "d"(d));
}
__device__ __forceinline__ void ffma2(double& acc, double a, double b) {
    asm("fma.rn.f32x2 %0, %1, %2, %0;" : "+d"(acc) : "d"(a), "d"(b));
}

// ---------------------------------------------------------------------------
// Phase1: block = 128 threads / 256 nodes. 8 k-chunks of 16 floats staged to
// smem (coalesced, read once). Lane owns nodes (w*64+lane, +32): W-broadcast
// LDS amortized over 64 nodes/warp; FFMA2 floor ~4.2us chip-wide.
// ---------------------------------------------------------------------------
__global__ void __launch_bounds__(128, 4)
phase1_kernel(const float* __restrict__ x, const float* __restrict__ W,
              int n_nodes) {
    __shared__ float4 xs[256 * 5];   // 256 nodes x 4 f4 (+1 f4 pad: stride 20w)
    __shared__ float4 ws[18 * 32];   // ws[j][c]: j<9 Wr rows, j>=9 Wc rows
    int t = threadIdx.x;
    int w = t >> 5, lane = t & 31;
    int nbase = blockIdx.x * 256;
    int maxn = n_nodes - nbase;

    const float4* Wf4 = (const float4*)W;
    for (int i = t; i < 18 * 32; i += 128) {
        int j = i >> 5, c = i & 31;
        ws[i] = (j < 9) ? Wf4[j * 64 + c] : Wf4[(j - 9) * 64 + 32 + c];
    }

    double accA[18], accB[18];
    #pragma unroll
    for (int j = 0; j < 18; j++) { accA[j] = 0.0; accB[j] = 0.0; }

    const float4* xf4 = (const float4*)x;
    int la = w * 64 + lane;          // local node A
    int lb = la + 32;                // local node B

    for (int kc = 0; kc < 8; kc++) {
        __syncthreads();             // xs reuse fence (also orders ws once)
        #pragma unroll
        for (int q = 0; q < 8; q++) {
            int i = q * 128 + t;     // 0..1023 f4 of this chunk
            int node = i >> 2, c = i & 3;
            float4 v = make_float4(0.f, 0.f, 0.f, 0.f);
            if (node < maxn) v = xf4[(size_t)(nbase + node) * 32 + kc * 4 + c];
            xs[node * 5 + c] = v;
        }
        __syncthreads();
        #pragma unroll
        for (int c = 0; c < 4; c++) {
            float4 xa = xs[la * 5 + c];
            float4 xb = xs[lb * 5 + c];
            double a01 = pk2(xa.x, xa.y), a23 = pk2(xa.z, xa.w);
            double b01 = pk2(xb.x, xb.y), b23 = pk2(xb.z, xb.w);
            #pragma unroll
            for (int j = 0; j < 18; j++) {
                double2 wv = *(const double2*)&ws[j * 32 + kc * 4 + c];
                ffma2(accA[j], a01, wv.x);
                ffma2(accA[j], a23, wv.y);
                ffma2(accB[j], b01, wv.x);
                ffma2(accB[j], b23, wv.y);
            }
        }
    }

    float rA[18], rB[18];
    #pragma unroll
    for (int j = 0; j < 18; j++) {
        float lo, hi;
        upk2(accA[j], lo, hi); rA[j] = lo + hi;
        upk2(accB[j], lo, hi); rB[j] = lo + hi;
    }

    int nA = nbase + la, nB = nbase + lb;
    if (nA < n_nodes) {
        float* ru = g_uv + (size_t)nA * PAD;
        ((float4*)ru)[0] = make_float4(rA[0], rA[1], rA[2], rA[3]);
        ((float4*)ru)[1] = make_float4(rA[4], rA[5], rA[6], rA[7]);
        ((float4*)ru)[2] = make_float4(rA[8], 0.f, 0.f, 0.f);
        float* rv = g_uv + VOFF + (size_t)nA * PAD;
        ((float4*)rv)[0] = make_float4(rA[9], rA[10], rA[11], rA[12]);
        ((float4*)rv)[1] = make_float4(rA[13], rA[14], rA[15], rA[16]);
        ((float4*)rv)[2] = make_float4(rA[17], 0.f, 0.f, 0.f);
    }
    if (nB < n_nodes) {
        float* ru = g_uv + (size_t)nB * PAD;
        ((float4*)ru)[0] = make_float4(rB[0], rB[1], rB[2], rB[3]);
        ((float4*)ru)[1] = make_float4(rB[4], rB[5], rB[6], rB[7]);
        ((float4*)ru)[2] = make_float4(rB[8], 0.f, 0.f, 0.f);
        float* rv = g_uv + VOFF + (size_t)nB * PAD;
        ((float4*)rv)[0] = make_float4(rB[9], rB[10], rB[11], rB[12]);
        ((float4*)rv)[1] = make_float4(rB[13], rB[14], rB[15], rB[16]);
        ((float4*)rv)[2] = make_float4(rB[17], 0.f, 0.f, 0.f);
    }
}

// ---------------------------------------------------------------------------
// tanh via XLA's f32 Pade (P deg-6 / Q deg-3 in s=t^2), 1 MUFU rcp.
// ---------------------------------------------------------------------------
__device__ __forceinline__ float tanh_xla(float x) {
    float t = fminf(fmaxf(x, -7.90531111f), 7.90531111f);
    float s = t * t;
    float p = fmaf(s, -2.76076847742355e-16f, 2.00018790482477e-13f);
    p = fmaf(p, s, -8.60467152213735e-11f);
    p = fmaf(p, s, 5.12229709037114e-08f);
    p = fmaf(p, s, 1.48572235717979e-05f);
    p = fmaf(p, s, 6.37261928875436e-04f);
    p = fmaf(p, s, 4.89352455891786e-03f);
    float q = fmaf(s, 1.19825839466702e-06f, 1.18534705686654e-04f);
    q = fmaf(q, s, 2.26843463243900e-03f);
    q = fmaf(q, s, 4.89352518554385e-03f);
    return __fdividef(t * p, q);
}

// ---------------------------------------------------------------------------
// Phase2: warp = 16 groups (2 clusters of 8); lane = grp*4+p. Vector idx
// loads; 12 gather LDG.128 hoisted (MLP 12); tanh predicated to j<9.
// ---------------------------------------------------------------------------
__global__ void __launch_bounds__(128)
phase2_kernel(const void* __restrict__ eidx, float* __restrict__ out,
              int n_groups, int E) {
    __shared__ float stage[4][144];
    int w = threadIdx.x >> 5, lane = threadIdx.x & 31;
    int grp = lane >> 2, p = lane & 3;

    int gbase = ((int)blockIdx.x * 4 + w) * 16;
    if (gbase >= n_groups) return;
    int gvalid = n_groups - gbase;
    if (gvalid > 16) gvalid = 16;
    int nedge = gvalid * 3;
    int e0 = gbase * 3;

    unsigned hwp = ((const unsigned*)eidx)[2 * lane + 1];
    bool is64 = (__ballot_sync(FULL, hwp != 0u) == 0u);

    int rx = 0, ry = 0, cx = 0, cy = 0;
    if (is64) {
        const longlong2* p2 = (const longlong2*)eidx;
        if (2 * lane + 2 <= nedge) {
            longlong2 R = p2[(e0 >> 1) + lane];
            longlong2 C = p2[(((size_t)E + e0) >> 1) + lane];
            rx = (int)R.x; ry = (int)R.y; cx = (int)C.x; cy = (int)C.y;
        } else if (2 * lane < nedge) {
            const long long* p1 = (const long long*)eidx;
            rx = (int)p1[e0 + 2 * lane];
            cx = (int)p1[(size_t)E + e0 + 2 * lane];
        }
    } else {
        const int2* p2 = (const int2*)eidx;
        if (2 * lane + 2 <= nedge) {
            int2 R = p2[(e0 >> 1) + lane];
            int2 C = p2[((E + e0) >> 1) + lane];
            rx = R.x; ry = R.y; cx = C.x; cy = C.y;
        } else if (2 * lane < nedge) {
            const int* p1 = (const int*)eidx;
            rx = p1[e0 + 2 * lane];
            cx = p1[E + e0 + 2 * lane];
        }
    }
    rx = min(max(rx, 0), MAX_NODES - 1) * PAD;
    ry = min(max(ry, 0), MAX_NODES - 1) * PAD;
    cx = VOFF + min(max(cx, 0), MAX_NODES - 1) * PAD;
    cy = VOFF + min(max(cy, 0), MAX_NODES - 1) * PAD;

    float4 ga[2][3], gb[2][3];
    #pragma unroll
    for (int c = 0; c < 2; c++) {
        #pragma unroll
        for (int i = 0; i < 3; i++) {
            int e = c * 24 + grp * 3 + i;     // edge slot within warp (0..47)
            int src = e >> 1;
            int rlo = __shfl_sync(FULL, rx, src);
            int rhi = __shfl_sync(FULL, ry, src);
            int clo = __shfl_sync(FULL, cx, src);
            int chi = __shfl_sync(FULL, cy, src);
            int oR = (e & 1) ? rhi : rlo;
            int oC = (e & 1) ? chi : clo;
            ga[c][i] = *(const float4*)(g_uv + oR + p * 4);
            gb[c][i] = *(const float4*)(g_uv + oC + p * 4);
        }
    }

    #pragma unroll
    for (int c = 0; c < 2; c++) {
        float ax = ga[c][0].x + ga[c][1].x + ga[c][2].x
                 + gb[c][0].x + gb[c][1].x + gb[c][2].x;
        float ay = ga[c][0].y + ga[c][1].y + ga[c][2].y
                 + gb[c][0].y + gb[c][1].y + gb[c][2].y;
        float az = ga[c][0].z + ga[c][1].z + ga[c][2].z
                 + gb[c][0].z + gb[c][1].z + gb[c][2].z;
        float aw = ga[c][0].w + ga[c][1].w + ga[c][2].w
                 + gb[c][0].w + gb[c][1].w + gb[c][2].w;
        int jb = 4 * p;
        float* sw = stage[w] + (c * 8 + grp) * 9 + jb;
        if (jb     < 9) sw[0] = tanh_xla(ax);
        if (jb + 1 < 9) sw[1] = tanh_xla(ay);
        if (jb + 2 < 9) sw[2] = tanh_xla(az);
        if (jb + 3 < 9) sw[3] = tanh_xla(aw);
    }
    __syncwarp();

    // 16 groups * 9 = 144 contiguous floats = 36 f4; guard by valid count
    int nfl = gvalid * 9;
    float* ob = out + (size_t)gbase * 9;
    const float* sb = stage[w];
    #pragma unroll
    for (int q = 0; q < 2; q++) {
        int idx = q * 32 + lane;
        if (idx < 36) {
            int f0 = idx * 4;
            if (f0 + 4 <= nfl) {
                *(float4*)(ob + f0) = *(const float4*)(sb + f0);
            } else if (f0 < nfl) {
                for (int k = f0; k < nfl; k++) ob[k] = sb[k];
            }
        }
    }
}

// ---------------------------------------------------------------------------
extern "C" void kernel_launch(void* const* d_in, const int* in_sizes, int n_in,
                              void* d_out, int out_size) {
    const float* x    = (const float*)d_in[0];   // [n_nodes, 128] fp32
    const float* W    = (const float*)d_in[1];   // [9, 256] fp32
    const void*  eidx = d_in[2];                 // [2, E] int32 or int64

    int n_nodes  = in_sizes[0] / HID;
    if (n_nodes > MAX_NODES) n_nodes = MAX_NODES;
    int n_groups = out_size / 9;
    int E = 3 * n_groups;

    phase1_kernel<<<(n_nodes + 255) / 256, 128>>>(x, W, n_nodes);
    phase2_kernel<<<(n_groups + 63) / 64, 128>>>(eidx, (float*)d_out,
                                                 n_groups, E);
}

// round 8
// speedup vs baseline: 2.5462x; 1.1231x over previous
#include <cuda_runtime.h>

// out[g] = tanh( sum_{i<3} x[row_{3g+i}]·Wr + x[col_{3g+i}]·Wc )
// Phase1: FFMA2 mini-GEMM, W packed (j-pair,k-pair) double2 in smem (broadcast
//         LDS), 2 nodes/thread, dependency distance 9 between same-acc FFMA2s.
// Phase2: warp=16 groups, 2 clusters processed sequentially (low regs/high occ),
//         6 gather LDG.128 per cluster, Pade tanh, coalesced staged stores.

#define HID 128
#define PAD 16
#define MAX_NODES 60000
#define VOFF (MAX_NODES * PAD)
#define FULL 0xffffffffu

__device__ float g_uv[2 * MAX_NODES * PAD];

// ---- f32x2 packed helpers ----
__device__ __forceinline__ double pk2(float lo, float hi) {
    double d;
    asm("mov.b64 %0, {%1, %2};" : "=d"(d) : "f"(lo), "f"(hi));
    return d;
}
__device__ __forceinline__ double dup2(float v) {
    double d;
    asm("mov.b64 %0, {%1, %1};" : "=d"(d) : "f"(v));
    return d;
}
__device__ __forceinline__ void upk2(double d, float& lo, float& hi) {
    asm("mov.b64 {%0, %1}, %2;" : "=f"(lo), "=f"(hi) : "d"(d));
}
__device__ __forceinline__ void ffma2(double& acc, double a, double b) {
    asm("fma.rn.f32x2 %0, %1, %2, %0;" : "+d"(acc) : "d"(a), "d"(b));
}

// ---------------------------------------------------------------------------
// Phase1: 128 threads, 256 nodes/block. W packed once into smem:
// wq[k2][j2] = double2{ pk2(W(j0,k0),W(j1,k0)), pk2(W(j0,k1),W(j1,k1)) }
// where j in [0,18) spans u(0..8) then v(9..17), (j0,j1)=(2j2,2j2+1),
// (k0,k1)=(2k2,2k2+1). x staged per 16-float chunk (stride-20 smem rows,
// conflict-free LDS.128). Each thread: nodes (t, t+128), 9 double accs each.
// ---------------------------------------------------------------------------
__global__ void __launch_bounds__(128)
phase1_kernel(const float* __restrict__ x, const float* __restrict__ W,
              int n_nodes) {
    __shared__ double2 wq[64 * 9];     // 9216 B
    __shared__ float   xs[256 * 20];   // 20480 B, stride 20 floats
    int t = threadIdx.x;
    int nbase = blockIdx.x * 256;

    for (int i = t; i < 576; i += 128) {
        int k2 = i / 9, j2 = i - k2 * 9;
        int j0 = 2 * j2, j1 = j0 + 1;
        int k0 = 2 * k2;
        float a00 = (j0 < 9) ? W[j0 * 256 + k0]     : W[(j0 - 9) * 256 + 128 + k0];
        float a01 = (j0 < 9) ? W[j0 * 256 + k0 + 1] : W[(j0 - 9) * 256 + 128 + k0 + 1];
        float a10 = (j1 < 9) ? W[j1 * 256 + k0]     : W[(j1 - 9) * 256 + 128 + k0];
        float a11 = (j1 < 9) ? W[j1 * 256 + k0 + 1] : W[(j1 - 9) * 256 + 128 + k0 + 1];
        double2 d;
        d.x = pk2(a00, a10);
        d.y = pk2(a01, a11);
        wq[k2 * 9 + j2] = d;
    }

    double accA[9], accB[9];
    #pragma unroll
    for (int j = 0; j < 9; j++) { accA[j] = 0.0; accB[j] = 0.0; }

    const float4* xf4 = (const float4*)x;
    for (int ch = 0; ch < 8; ch++) {
        __syncthreads();               // prev-chunk reads done (and wq built)
        #pragma unroll
        for (int q = 0; q < 8; q++) {
            int i = q * 128 + t;       // f4 slot 0..1023
            int node = i >> 2, cc = i & 3;
            int gn = nbase + node;
            float4 v = make_float4(0.f, 0.f, 0.f, 0.f);
            if (gn < n_nodes) v = xf4[(size_t)gn * 32 + ch * 4 + cc];
            *(float4*)&xs[node * 20 + cc * 4] = v;
        }
        __syncthreads();

        #pragma unroll
        for (int kk = 0; kk < 8; kk += 2) {       // two k2 per x LDS.128
            float4 xa = *(const float4*)&xs[t * 20 + kk * 2];
            float4 xb = *(const float4*)&xs[(t + 128) * 20 + kk * 2];
            #pragma unroll
            for (int s = 0; s < 2; s++) {
                int k2g = ch * 8 + kk + s;
                const double2* wr = &wq[k2g * 9];
                double2 w[9];
                #pragma unroll
                for (int j = 0; j < 9; j++) w[j] = wr[j];
                double xal = dup2(s ? xa.z : xa.x);
                double xah = dup2(s ? xa.w : xa.y);
                double xbl = dup2(s ? xb.z : xb.x);
                double xbh = dup2(s ? xb.w : xb.y);
                #pragma unroll
                for (int j = 0; j < 9; j++) ffma2(accA[j], xal, w[j].x);
                #pragma unroll
                for (int j = 0; j < 9; j++) ffma2(accA[j], xah, w[j].y);
                #pragma unroll
                for (int j = 0; j < 9; j++) ffma2(accB[j], xbl, w[j].x);
                #pragma unroll
                for (int j = 0; j < 9; j++) ffma2(accB[j], xbh, w[j].y);
            }
        }
    }

    int nA = nbase + t, nB = nbase + 128 + t;
    if (nA < n_nodes) {
        float r[18];
        #pragma unroll
        for (int j = 0; j < 9; j++) upk2(accA[j], r[2 * j], r[2 * j + 1]);
        float* ru = g_uv + (size_t)nA * PAD;
        ((float4*)ru)[0] = make_float4(r[0], r[1], r[2], r[3]);
        ((float4*)ru)[1] = make_float4(r[4], r[5], r[6], r[7]);
        ((float4*)ru)[2] = make_float4(r[8], 0.f, 0.f, 0.f);
        float* rv = g_uv + VOFF + (size_t)nA * PAD;
        ((float4*)rv)[0] = make_float4(r[9], r[10], r[11], r[12]);
        ((float4*)rv)[1] = make_float4(r[13], r[14], r[15], r[16]);
        ((float4*)rv)[2] = make_float4(r[17], 0.f, 0.f, 0.f);
    }
    if (nB < n_nodes) {
        float r[18];
        #pragma unroll
        for (int j = 0; j < 9; j++) upk2(accB[j], r[2 * j], r[2 * j + 1]);
        float* ru = g_uv + (size_t)nB * PAD;
        ((float4*)ru)[0] = make_float4(r[0], r[1], r[2], r[3]);
        ((float4*)ru)[1] = make_float4(r[4], r[5], r[6], r[7]);
        ((float4*)ru)[2] = make_float4(r[8], 0.f, 0.f, 0.f);
        float* rv = g_uv + VOFF + (size_t)nB * PAD;
        ((float4*)rv)[0] = make_float4(r[9], r[10], r[11], r[12]);
        ((float4*)rv)[1] = make_float4(r[13], r[14], r[15], r[16]);
        ((float4*)rv)[2] = make_float4(r[17], 0.f, 0.f, 0.f);
    }
}

// ---------------------------------------------------------------------------
// tanh via XLA's f32 Pade (P deg-6 / Q deg-3 in s=t^2), 1 MUFU rcp.
// ---------------------------------------------------------------------------
__device__ __forceinline__ float tanh_xla(float x) {
    float t = fminf(fmaxf(x, -7.90531111f), 7.90531111f);
    float s = t * t;
    float p = fmaf(s, -2.76076847742355e-16f, 2.00018790482477e-13f);
    p = fmaf(p, s, -8.60467152213735e-11f);
    p = fmaf(p, s, 5.12229709037114e-08f);
    p = fmaf(p, s, 1.48572235717979e-05f);
    p = fmaf(p, s, 6.37261928875436e-04f);
    p = fmaf(p, s, 4.89352455891786e-03f);
    float q = fmaf(s, 1.19825839466702e-06f, 1.18534705686654e-04f);
    q = fmaf(q, s, 2.26843463243900e-03f);
    q = fmaf(q, s, 4.89352518554385e-03f);
    return __fdividef(t * p, q);
}

// ---------------------------------------------------------------------------
// Phase2: warp = 16 groups; lane = grp*4+p. Two 8-group clusters processed
// sequentially (unroll 1) to keep ~6 gather f4s live -> low regs, high occ.
// ---------------------------------------------------------------------------
__global__ void __launch_bounds__(128)
phase2_kernel(const void* __restrict__ eidx, float* __restrict__ out,
              int n_groups, int E) {
    __shared__ float stage[4][144];
    int w = threadIdx.x >> 5, lane = threadIdx.x & 31;
    int grp = lane >> 2, p = lane & 3;

    int gbase = ((int)blockIdx.x * 4 + w) * 16;
    if (gbase >= n_groups) return;
    int gvalid = n_groups - gbase;
    if (gvalid > 16) gvalid = 16;
    int nedge = gvalid * 3;
    int e0 = gbase * 3;

    unsigned hwp = ((const unsigned*)eidx)[2 * lane + 1];
    bool is64 = (__ballot_sync(FULL, hwp != 0u) == 0u);

    int rx = 0, ry = 0, cx = 0, cy = 0;
    if (is64) {
        const longlong2* p2 = (const longlong2*)eidx;
        if (2 * lane + 2 <= nedge) {
            longlong2 R = p2[(e0 >> 1) + lane];
            longlong2 C = p2[(((size_t)E + e0) >> 1) + lane];
            rx = (int)R.x; ry = (int)R.y; cx = (int)C.x; cy = (int)C.y;
        } else if (2 * lane < nedge) {
            const long long* p1 = (const long long*)eidx;
            rx = (int)p1[e0 + 2 * lane];
            cx = (int)p1[(size_t)E + e0 + 2 * lane];
        }
    } else {
        const int2* p2 = (const int2*)eidx;
        if (2 * lane + 2 <= nedge) {
            int2 R = p2[(e0 >> 1) + lane];
            int2 C = p2[((E + e0) >> 1) + lane];
            rx = R.x; ry = R.y; cx = C.x; cy = C.y;
        } else if (2 * lane < nedge) {
            const int* p1 = (const int*)eidx;
            rx = p1[e0 + 2 * lane];
            cx = p1[E + e0 + 2 * lane];
        }
    }
    rx = min(max(rx, 0), MAX_NODES - 1) * PAD;
    ry = min(max(ry, 0), MAX_NODES - 1) * PAD;
    cx = VOFF + min(max(cx, 0), MAX_NODES - 1) * PAD;
    cy = VOFF + min(max(cy, 0), MAX_NODES - 1) * PAD;

    #pragma unroll 1
    for (int c = 0; c < 2; c++) {
        float4 ga[3], gb[3];
        #pragma unroll
        for (int i = 0; i < 3; i++) {
            int e = c * 24 + grp * 3 + i;
            int src = e >> 1;
            int rlo = __shfl_sync(FULL, rx, src);
            int rhi = __shfl_sync(FULL, ry, src);
            int clo = __shfl_sync(FULL, cx, src);
            int chi = __shfl_sync(FULL, cy, src);
            int oR = (e & 1) ? rhi : rlo;
            int oC = (e & 1) ? chi : clo;
            ga[i] = *(const float4*)(g_uv + oR + p * 4);
            gb[i] = *(const float4*)(g_uv + oC + p * 4);
        }
        float ax = ga[0].x + ga[1].x + ga[2].x + gb[0].x + gb[1].x + gb[2].x;
        float ay = ga[0].y + ga[1].y + ga[2].y + gb[0].y + gb[1].y + gb[2].y;
        float az = ga[0].z + ga[1].z + ga[2].z + gb[0].z + gb[1].z + gb[2].z;
        float aw = ga[0].w + ga[1].w + ga[2].w + gb[0].w + gb[1].w + gb[2].w;

        int jb = 4 * p;
        float* sw = stage[w] + (c * 8 + grp) * 9 + jb;
        if (jb     < 9) sw[0] = tanh_xla(ax);
        if (jb + 1 < 9) sw[1] = tanh_xla(ay);
        if (jb + 2 < 9) sw[2] = tanh_xla(az);
        if (jb + 3 < 9) sw[3] = tanh_xla(aw);
    }
    __syncwarp();

    int nfl = gvalid * 9;
    float* ob = out + (size_t)gbase * 9;
    const float* sb = stage[w];
    #pragma unroll
    for (int q = 0; q < 2; q++) {
        int idx = q * 32 + lane;
        if (idx < 36) {
            int f0 = idx * 4;
            if (f0 + 4 <= nfl) {
                *(float4*)(ob + f0) = *(const float4*)(sb + f0);
            } else if (f0 < nfl) {
                for (int k = f0; k < nfl; k++) ob[k] = sb[k];
            }
        }
    }
}

// ---------------------------------------------------------------------------
extern "C" void kernel_launch(void* const* d_in, const int* in_sizes, int n_in,
                              void* d_out, int out_size) {
    const float* x    = (const float*)d_in[0];   // [n_nodes, 128] fp32
    const float* W    = (const float*)d_in[1];   // [9, 256] fp32
    const void*  eidx = d_in[2];                 // [2, E] int32 or int64

    int n_nodes  = in_sizes[0] / HID;
    if (n_nodes > MAX_NODES) n_nodes = MAX_NODES;
    int n_groups = out_size / 9;
    int E = 3 * n_groups;

    phase1_kernel<<<(n_nodes + 255) / 256, 128>>>(x, W, n_nodes);
    phase2_kernel<<<(n_groups + 63) / 64, 128>>>(eidx, (float*)d_out,
                                                 n_groups, E);
}